// round 8
// baseline (speedup 1.0000x reference)
#include <cuda_runtime.h>
#include <cuda_fp16.h>
#include <cstdint>
#include <cstddef>

// ---------------------------------------------------------------------------
// LSTM cell, B=65536, I=H=256. Baseline-PTX path (harness ptxas targets
// sm_103 without the 'a' feature set -> no tcgen05; cp.async + ldmatrix +
// mma.sync.m16n8k16.f32.f16 only).
//
// Pass 1 (single kernel): [x|h] -> fp16 scratch (B x 512), [Wi|Wh] -> fp16.
// Pass 2: gates[B,1024] = XH @ W^T. CTA tile M=128 x N=128 (4 gates x 32
//         h-cols -> LSTM elementwise stays CTA-local), 128 threads, 2x2 warp
//         grid with 64x64 warp tiles (LDSM:HMMA = 1:4, smem reread halved),
//         3-stage cp.async pipeline, 96KB smem -> 2 CTAs/SM. Fused epilogue.
// Output: d_out[0 : B*H] = h_new, d_out[B*H : 2*B*H] = c_new.
// ---------------------------------------------------------------------------

#define BATCH   65536
#define HID     256
#define KDIM    512
#define M_TILE  128
#define KC      64            // halves per K chunk = 128 bytes per row
#define NCHUNK  8             // 512 / 64
#define NSTG    3
#define STAGE_A 16384         // 128 rows * 128B
#define STAGE_B 16384         // 128 rows * 128B
#define STAGE_BYTES 32768
#define DYN_SMEM (NSTG * STAGE_BYTES)   // 98304 -> 2 CTAs/SM
#define SG_STRIDE 132         // padded float stride for epilogue staging

// fp16 scratch (module-static device memory; no runtime allocation)
__device__ __half xh16g[(size_t)BATCH * KDIM];   // 64 MB
__device__ __half w16g[1024 * KDIM];             // 1 MB

// ---------------- helpers ----------------

__device__ __forceinline__ uint32_t swz(uint32_t o) {
    return o ^ ((o >> 3) & 0x70);          // xor bits[4:6] with bits[7:9]
}

#define CP_ASYNC16(dst, src) \
    asm volatile("cp.async.cg.shared.global [%0], [%1], 16;" \
                 :: "r"(dst), "l"(src) : "memory")

#define CP_COMMIT() asm volatile("cp.async.commit_group;" ::: "memory")

#define LDSM4(R, addr) \
    asm volatile("ldmatrix.sync.aligned.m8n8.x4.shared.b16 {%0,%1,%2,%3}, [%4];" \
                 : "=r"((R)[0]), "=r"((R)[1]), "=r"((R)[2]), "=r"((R)[3]) \
                 : "r"(addr))

#define MMA16816(d, a, b0, b1) \
    asm volatile("mma.sync.aligned.m16n8k16.row.col.f32.f16.f16.f32 " \
                 "{%0,%1,%2,%3},{%4,%5,%6,%7},{%8,%9},{%0,%1,%2,%3};" \
                 : "+f"((d)[0]), "+f"((d)[1]), "+f"((d)[2]), "+f"((d)[3]) \
                 : "r"((a)[0]), "r"((a)[1]), "r"((a)[2]), "r"((a)[3]), \
                   "r"(b0), "r"(b1))

__device__ __forceinline__ float sigf(float x) {
    return __fdividef(1.0f, 1.0f + __expf(-x));
}
__device__ __forceinline__ float tanhf_fast(float x) {
    return 1.0f - __fdividef(2.0f, 1.0f + __expf(2.0f * x));
}

// ---------------- pass 1: fp32 -> fp16 concat convert (single kernel) ----
// rows [0, BATCH):            xh16g[r*512+k] = k<256 ? x[r,k] : h[r,k-256]
// rows [BATCH, BATCH+1024):   w16g [r*512+k] = k<256 ? Wi[r,k] : Wh[r,k-256]

__global__ void __launch_bounds__(256) conv_all_kernel(const float* __restrict__ x,
                                                       const float* __restrict__ h,
                                                       const float* __restrict__ Wi,
                                                       const float* __restrict__ Wh)
{
    size_t i = ((size_t)blockIdx.x * blockDim.x + threadIdx.x) * 8;
    if (i >= (size_t)(BATCH + 1024) * KDIM) return;
    int r = (int)(i >> 9);
    int k = (int)(i & 511);
    const float* A;
    const float* Bm;
    __half* dst;
    size_t row;
    if (r < BATCH) { A = x;  Bm = h;  dst = xh16g; row = (size_t)r; }
    else           { A = Wi; Bm = Wh; dst = w16g;  row = (size_t)(r - BATCH); }
    const float* s = (k < 256) ? (A + row * 256 + k) : (Bm + row * 256 + (k - 256));
    float4 f0 = ((const float4*)s)[0];
    float4 f1 = ((const float4*)s)[1];
    __half2 h0 = __floats2half2_rn(f0.x, f0.y);
    __half2 h1 = __floats2half2_rn(f0.z, f0.w);
    __half2 h2 = __floats2half2_rn(f1.x, f1.y);
    __half2 h3 = __floats2half2_rn(f1.z, f1.w);
    uint4 v;
    v.x = *(uint32_t*)&h0; v.y = *(uint32_t*)&h1;
    v.z = *(uint32_t*)&h2; v.w = *(uint32_t*)&h3;
    *(uint4*)(dst + row * KDIM + k) = v;
}

// ---------------- pass 2: GEMM + LSTM ----------------
// B tile rows: tile row r -> gate g = r>>5, jj = r&31, weight row g*256+jbase+jj

__device__ __forceinline__ void issue_stage(uint32_t smb, int stage, int kc,
                                            int tid, int mrow, int jbase)
{
    const uint32_t abase = smb + stage * STAGE_BYTES;
    const uint32_t bbase = abase + STAGE_A;
    #pragma unroll
    for (int j = 0; j < 16; ++j) {
        const int slot = tid + j * 128;          // 0..2047
        if (slot < 1024) {                       // A: 128 rows x 8 segs of 16B
            const int row = slot >> 3, seg = slot & 7;
            const uint32_t d = abase + swz(row * 128 + seg * 16);
            const __half* src = xh16g + ((size_t)(mrow + row) << 9) + kc * KC + seg * 8;
            CP_ASYNC16(d, src);
        } else {                                 // B: 128 rows x 8 segs
            const int t = slot - 1024;
            const int row = t >> 3, seg = t & 7;
            const int wrow = ((row >> 5) << 8) + jbase + (row & 31);
            const uint32_t d = bbase + swz(row * 128 + seg * 16);
            const __half* src = w16g + ((size_t)wrow << 9) + kc * KC + seg * 8;
            CP_ASYNC16(d, src);
        }
    }
}

extern "C" __global__ void __launch_bounds__(128, 2)
lstm_gemm_kernel(const float* __restrict__ c_in,
                 const float* __restrict__ bi,
                 const float* __restrict__ bh,
                 float* __restrict__ h_out,
                 float* __restrict__ c_out)
{
    extern __shared__ __align__(1024) char dynsmem[];
    __shared__ float sbias[128];

    const int tid  = threadIdx.x;
    const int lane = tid & 31;
    const int wid  = tid >> 5;
    const int wm   = wid >> 1;           // warp row 0..1 (64 m-rows each)
    const int wn   = wid & 1;            // warp col 0..1 (64 tile-cols each)

    const int m_tile = (int)(blockIdx.x >> 3);
    const int jslice = (int)(blockIdx.x & 7);
    const int mrow   = m_tile * M_TILE;
    const int jbase  = jslice * 32;

    const uint32_t smb = (uint32_t)__cvta_generic_to_shared(dynsmem);

    // bias sums for this CTA's (gate, jj) columns: sbias[g*32 + jj]
    if (tid < 128) {
        const int g = tid >> 5, jj = tid & 31;
        const int col = g * 256 + jbase + jj;
        sbias[tid] = bi[col] + bh[col];
    }

    float acc[4][8][4];
    #pragma unroll
    for (int mt = 0; mt < 4; ++mt)
        #pragma unroll
        for (int nt = 0; nt < 8; ++nt)
            #pragma unroll
            for (int q = 0; q < 4; ++q) acc[mt][nt][q] = 0.0f;

    // prologue: fill first NSTG-1 = 2 stages
    #pragma unroll
    for (int s = 0; s < NSTG - 1; ++s) {
        issue_stage(smb, s, s, tid, mrow, jbase);
        CP_COMMIT();
    }

    // ldmatrix per-lane offsets (within a 128B-wide swizzled row layout)
    const int a_row0 = wm * 64 + (lane & 15);
    const int a_koff = (lane >> 4) * 16;
    const int b_rowc = wn * 64 + ((lane >> 4) << 3) + (lane & 7);
    const int b_koff = ((lane >> 3) & 1) * 16;

    int stage = 0;
    for (int k = 0; k < NCHUNK; ++k) {
        asm volatile("cp.async.wait_group 1;" ::: "memory");
        __syncthreads();

        if (k + NSTG - 1 < NCHUNK) {
            int ns = stage + (NSTG - 1);
            if (ns >= NSTG) ns -= NSTG;
            issue_stage(smb, ns, k + NSTG - 1, tid, mrow, jbase);
        }
        CP_COMMIT();

        const uint32_t abase = smb + stage * STAGE_BYTES;
        const uint32_t bbase = abase + STAGE_A;

        #pragma unroll
        for (int kt = 0; kt < 4; ++kt) {
            uint32_t aF[4][4];
            #pragma unroll
            for (int mt = 0; mt < 4; ++mt) {
                const uint32_t o = (uint32_t)((a_row0 + mt * 16) * 128 + kt * 32 + a_koff);
                LDSM4(aF[mt], abase + swz(o));
            }
            uint32_t bF[4][4];
            #pragma unroll
            for (int nt2 = 0; nt2 < 4; ++nt2) {
                const uint32_t o = (uint32_t)((b_rowc + nt2 * 16) * 128 + kt * 32 + b_koff);
                LDSM4(bF[nt2], bbase + swz(o));
            }
            #pragma unroll
            for (int mt = 0; mt < 4; ++mt)
                #pragma unroll
                for (int nt = 0; nt < 8; ++nt)
                    MMA16816(acc[mt][nt], aF[mt],
                             bF[nt >> 1][(nt & 1) * 2], bF[nt >> 1][(nt & 1) * 2 + 1]);
        }

        if (++stage == NSTG) stage = 0;
    }
    __syncthreads();   // pipeline smem -> epilogue staging reuse

    // stage gates through smem: sg[r * SG_STRIDE + tilecol], tilecol = g*32+jj
    float* sg = (float*)dynsmem;
    {
        const int r0 = wm * 64 + (lane >> 2);
        const int c0 = wn * 64 + 2 * (lane & 3);
        #pragma unroll
        for (int mt = 0; mt < 4; ++mt)
            #pragma unroll
            for (int nt = 0; nt < 8; ++nt) {
                const int r = r0 + mt * 16;
                const int c = c0 + nt * 8;
                *(float2*)&sg[r * SG_STRIDE + c]       = make_float2(acc[mt][nt][0], acc[mt][nt][1]);
                *(float2*)&sg[(r + 8) * SG_STRIDE + c] = make_float2(acc[mt][nt][2], acc[mt][nt][3]);
            }
    }
    __syncthreads();

    // fused LSTM elementwise: 128 rows x 32 cols = 4096 outputs, 32/thread
    #pragma unroll 4
    for (int it = 0; it < 32; ++it) {
        const int idx = it * 128 + tid;
        const int r  = idx >> 5;
        const int jj = idx & 31;
        const float gi = sg[r * SG_STRIDE +      jj] + sbias[     jj];
        const float gf = sg[r * SG_STRIDE + 32 + jj] + sbias[32 + jj];
        const float gg = sg[r * SG_STRIDE + 64 + jj] + sbias[64 + jj];
        const float go = sg[r * SG_STRIDE + 96 + jj] + sbias[96 + jj];
        const size_t gp = (size_t)(mrow + r) * HID + jbase + jj;
        const float cc = sigf(gf) * c_in[gp] + sigf(gi) * tanhf_fast(gg);
        c_out[gp] = cc;
        h_out[gp] = sigf(go) * tanhf_fast(cc);
    }
}

// ---------------- host launcher ----------------

extern "C" void kernel_launch(void* const* d_in, const int* in_sizes, int n_in,
                              void* d_out, int out_size)
{
    (void)in_sizes; (void)n_in; (void)out_size;
    const float* x  = (const float*)d_in[0];
    const float* h  = (const float*)d_in[1];
    const float* c  = (const float*)d_in[2];
    const float* Wi = (const float*)d_in[3];
    const float* Wh = (const float*)d_in[4];
    const float* bi = (const float*)d_in[5];
    const float* bh = (const float*)d_in[6];
    float* hout = (float*)d_out;
    float* cout = hout + (size_t)BATCH * HID;

    // pass 1: single conversion kernel (xh + weights)
    {
        const size_t n = (size_t)(BATCH + 1024) * KDIM / 8;
        conv_all_kernel<<<(unsigned)((n + 255) / 256), 256>>>(x, h, Wi, Wh);
    }

    // pass 2: GEMM + LSTM. grid: 512 m-tiles x 8 j-slices (adjacent bids
    // share A rows -> L2 dedup). 2 CTAs/SM.
    cudaFuncSetAttribute(lstm_gemm_kernel,
                         cudaFuncAttributeMaxDynamicSharedMemorySize, DYN_SMEM);
    lstm_gemm_kernel<<<(BATCH / M_TILE) * 8, 128, DYN_SMEM>>>(c, bi, bh, hout, cout);
}

// round 9
// speedup vs baseline: 1.1887x; 1.1887x over previous
#include <cuda_runtime.h>
#include <cuda_fp16.h>
#include <cstdint>
#include <cstddef>

// ---------------------------------------------------------------------------
// LSTM cell, B=65536, I=H=256. Baseline-PTX path (harness ptxas targets
// sm_103 without the 'a' feature set -> no tcgen05; cp.async + ldmatrix +
// mma.sync only).
//
// Pass 1 (single kernel): [x|h] -> fp16 scratch (B x 512), [Wi|Wh] -> fp16.
// Pass 2: gates[B,1024] = XH @ W^T with mma.sync.m16n8k16 using **fp16
//         accumulators** (2x legacy-HMMA rate; per-instruction fp32 internal
//         sum, rounded once per MMA). Per-chunk f16 partial sums fold into an
//         f16x2 master accumulator (bias + LSTM math done in fp32 epilogue).
//         CTA tile M=128 x N=128 (4 gates x 32 h-cols -> epilogue CTA-local),
//         256 threads, 4x2 warp grid of 32x64 tiles, 3-stage cp.async
//         pipeline, 96KB smem -> 2 CTAs/SM (16 warps/SM).
// Output: d_out[0 : B*H] = h_new, d_out[B*H : 2*B*H] = c_new.
// ---------------------------------------------------------------------------

#define BATCH   65536
#define HID     256
#define KDIM    512
#define M_TILE  128
#define KC      64            // halves per K chunk = 128 bytes per row
#define NCHUNK  8             // 512 / 64
#define NSTG    3
#define STAGE_A 16384         // 128 rows * 128B
#define STAGE_B 16384         // 128 rows * 128B
#define STAGE_BYTES 32768
#define DYN_SMEM (NSTG * STAGE_BYTES)   // 98304 -> 2 CTAs/SM
#define SG_STRIDE 132         // padded float stride for epilogue staging

// fp16 scratch (module-static device memory; no runtime allocation)
__device__ __half xh16g[(size_t)BATCH * KDIM];   // 64 MB
__device__ __half w16g[1024 * KDIM];             // 1 MB

// ---------------- helpers ----------------

__device__ __forceinline__ uint32_t swz(uint32_t o) {
    return o ^ ((o >> 3) & 0x70);          // xor bits[4:6] with bits[7:9]
}

#define CP_ASYNC16(dst, src) \
    asm volatile("cp.async.cg.shared.global [%0], [%1], 16;" \
                 :: "r"(dst), "l"(src) : "memory")

#define CP_COMMIT() asm volatile("cp.async.commit_group;" ::: "memory")

#define LDSM4(R, addr) \
    asm volatile("ldmatrix.sync.aligned.m8n8.x4.shared.b16 {%0,%1,%2,%3}, [%4];" \
                 : "=r"((R)[0]), "=r"((R)[1]), "=r"((R)[2]), "=r"((R)[3]) \
                 : "r"(addr))

// fp16-accumulate MMA: first-kt form (C = 0) and chained form (C = D).
#define MMA16816H_Z(d, a, b0, b1) \
    asm volatile("mma.sync.aligned.m16n8k16.row.col.f16.f16.f16.f16 " \
                 "{%0,%1},{%2,%3,%4,%5},{%6,%7},{%8,%8};" \
                 : "=r"((d)[0]), "=r"((d)[1]) \
                 : "r"((a)[0]), "r"((a)[1]), "r"((a)[2]), "r"((a)[3]), \
                   "r"(b0), "r"(b1), "r"(0u))

#define MMA16816H(d, a, b0, b1) \
    asm volatile("mma.sync.aligned.m16n8k16.row.col.f16.f16.f16.f16 " \
                 "{%0,%1},{%2,%3,%4,%5},{%6,%7},{%0,%1};" \
                 : "+r"((d)[0]), "+r"((d)[1]) \
                 : "r"((a)[0]), "r"((a)[1]), "r"((a)[2]), "r"((a)[3]), \
                   "r"(b0), "r"(b1))

#define HADD2(d, a) \
    asm volatile("add.rn.f16x2 %0, %0, %1;" : "+r"(d) : "r"(a))

__device__ __forceinline__ float sigf(float x) {
    return __fdividef(1.0f, 1.0f + __expf(-x));
}
__device__ __forceinline__ float tanhf_fast(float x) {
    return 1.0f - __fdividef(2.0f, 1.0f + __expf(2.0f * x));
}

// ---------------- pass 1: fp32 -> fp16 concat convert (single kernel) ----
// rows [0, BATCH):            xh16g[r*512+k] = k<256 ? x[r,k] : h[r,k-256]
// rows [BATCH, BATCH+1024):   w16g [r*512+k] = k<256 ? Wi[r,k] : Wh[r,k-256]

__global__ void __launch_bounds__(256) conv_all_kernel(const float* __restrict__ x,
                                                       const float* __restrict__ h,
                                                       const float* __restrict__ Wi,
                                                       const float* __restrict__ Wh)
{
    size_t i = ((size_t)blockIdx.x * blockDim.x + threadIdx.x) * 8;
    if (i >= (size_t)(BATCH + 1024) * KDIM) return;
    int r = (int)(i >> 9);
    int k = (int)(i & 511);
    const float* A;
    const float* Bm;
    __half* dst;
    size_t row;
    if (r < BATCH) { A = x;  Bm = h;  dst = xh16g; row = (size_t)r; }
    else           { A = Wi; Bm = Wh; dst = w16g;  row = (size_t)(r - BATCH); }
    const float* s = (k < 256) ? (A + row * 256 + k) : (Bm + row * 256 + (k - 256));
    float4 f0 = ((const float4*)s)[0];
    float4 f1 = ((const float4*)s)[1];
    __half2 h0 = __floats2half2_rn(f0.x, f0.y);
    __half2 h1 = __floats2half2_rn(f0.z, f0.w);
    __half2 h2 = __floats2half2_rn(f1.x, f1.y);
    __half2 h3 = __floats2half2_rn(f1.z, f1.w);
    uint4 v;
    v.x = *(uint32_t*)&h0; v.y = *(uint32_t*)&h1;
    v.z = *(uint32_t*)&h2; v.w = *(uint32_t*)&h3;
    *(uint4*)(dst + row * KDIM + k) = v;
}

// ---------------- pass 2: GEMM + LSTM ----------------
// B tile rows: tile row r -> gate g = r>>5, jj = r&31, weight row g*256+jbase+jj

__device__ __forceinline__ void issue_stage(uint32_t smb, int stage, int kc,
                                            int tid, int mrow, int jbase)
{
    const uint32_t abase = smb + stage * STAGE_BYTES;
    const uint32_t bbase = abase + STAGE_A;
    #pragma unroll
    for (int j = 0; j < 8; ++j) {
        const int slot = tid + j * 256;          // 0..2047
        if (slot < 1024) {                       // A: 128 rows x 8 segs of 16B
            const int row = slot >> 3, seg = slot & 7;
            const uint32_t d = abase + swz(row * 128 + seg * 16);
            const __half* src = xh16g + ((size_t)(mrow + row) << 9) + kc * KC + seg * 8;
            CP_ASYNC16(d, src);
        } else {                                 // B: 128 rows x 8 segs
            const int t = slot - 1024;
            const int row = t >> 3, seg = t & 7;
            const int wrow = ((row >> 5) << 8) + jbase + (row & 31);
            const uint32_t d = bbase + swz(row * 128 + seg * 16);
            const __half* src = w16g + ((size_t)wrow << 9) + kc * KC + seg * 8;
            CP_ASYNC16(d, src);
        }
    }
}

extern "C" __global__ void __launch_bounds__(256, 2)
lstm_gemm_kernel(const float* __restrict__ c_in,
                 const float* __restrict__ bi,
                 const float* __restrict__ bh,
                 float* __restrict__ h_out,
                 float* __restrict__ c_out)
{
    extern __shared__ __align__(1024) char dynsmem[];
    __shared__ float sbias[128];

    const int tid  = threadIdx.x;
    const int lane = tid & 31;
    const int wid  = tid >> 5;
    const int wm   = wid >> 1;           // warp row 0..3 (32 m-rows each)
    const int wn   = wid & 1;            // warp col 0..1 (64 tile-cols each)

    const int m_tile = (int)(blockIdx.x >> 3);
    const int jslice = (int)(blockIdx.x & 7);
    const int mrow   = m_tile * M_TILE;
    const int jbase  = jslice * 32;

    const uint32_t smb = (uint32_t)__cvta_generic_to_shared(dynsmem);

    // bias sums for this CTA's (gate, jj) columns: sbias[g*32 + jj]
    if (tid < 128) {
        const int g = tid >> 5, jj = tid & 31;
        const int col = g * 256 + jbase + jj;
        sbias[tid] = bi[col] + bh[col];
    }

    // master accumulators: f16x2, [mt][nt][reg] reg0=(r,c|c+1), reg1=(r+8,..)
    uint32_t hmast[2][8][2];
    #pragma unroll
    for (int mt = 0; mt < 2; ++mt)
        #pragma unroll
        for (int nt = 0; nt < 8; ++nt) {
            hmast[mt][nt][0] = 0u;
            hmast[mt][nt][1] = 0u;
        }

    // prologue: fill first NSTG-1 = 2 stages
    #pragma unroll
    for (int s = 0; s < NSTG - 1; ++s) {
        issue_stage(smb, s, s, tid, mrow, jbase);
        CP_COMMIT();
    }

    // ldmatrix per-lane offsets (within a 128B-wide swizzled row layout)
    const int a_row0 = wm * 32 + (lane & 15);
    const int a_koff = (lane >> 4) * 16;
    const int b_rowc = wn * 64 + ((lane >> 4) << 3) + (lane & 7);
    const int b_koff = ((lane >> 3) & 1) * 16;

    int stage = 0;
    for (int k = 0; k < NCHUNK; ++k) {
        asm volatile("cp.async.wait_group 1;" ::: "memory");
        __syncthreads();

        if (k + NSTG - 1 < NCHUNK) {
            int ns = stage + (NSTG - 1);
            if (ns >= NSTG) ns -= NSTG;
            issue_stage(smb, ns, k + NSTG - 1, tid, mrow, jbase);
        }
        CP_COMMIT();

        const uint32_t abase = smb + stage * STAGE_BYTES;
        const uint32_t bbase = abase + STAGE_A;

        // per-chunk fp16 partial sums (4 MMA roundings over K=64)
        uint32_t hchk[2][8][2];

        #pragma unroll
        for (int kt = 0; kt < 4; ++kt) {
            uint32_t aF[2][4];
            #pragma unroll
            for (int mt = 0; mt < 2; ++mt) {
                const uint32_t o = (uint32_t)((a_row0 + mt * 16) * 128 + kt * 32 + a_koff);
                LDSM4(aF[mt], abase + swz(o));
            }
            uint32_t bF[4][4];
            #pragma unroll
            for (int nt2 = 0; nt2 < 4; ++nt2) {
                const uint32_t o = (uint32_t)((b_rowc + nt2 * 16) * 128 + kt * 32 + b_koff);
                LDSM4(bF[nt2], bbase + swz(o));
            }
            if (kt == 0) {
                #pragma unroll
                for (int mt = 0; mt < 2; ++mt)
                    #pragma unroll
                    for (int nt = 0; nt < 8; ++nt)
                        MMA16816H_Z(hchk[mt][nt], aF[mt],
                                    bF[nt >> 1][(nt & 1) * 2], bF[nt >> 1][(nt & 1) * 2 + 1]);
            } else {
                #pragma unroll
                for (int mt = 0; mt < 2; ++mt)
                    #pragma unroll
                    for (int nt = 0; nt < 8; ++nt)
                        MMA16816H(hchk[mt][nt], aF[mt],
                                  bF[nt >> 1][(nt & 1) * 2], bF[nt >> 1][(nt & 1) * 2 + 1]);
            }
        }

        // fold chunk sums into master (f16x2 adds on fma pipe)
        #pragma unroll
        for (int mt = 0; mt < 2; ++mt)
            #pragma unroll
            for (int nt = 0; nt < 8; ++nt) {
                HADD2(hmast[mt][nt][0], hchk[mt][nt][0]);
                HADD2(hmast[mt][nt][1], hchk[mt][nt][1]);
            }

        if (++stage == NSTG) stage = 0;
    }
    __syncthreads();   // pipeline smem -> epilogue staging reuse

    // stage gates through smem as fp32: sg[r * SG_STRIDE + g*32 + jj]
    float* sg = (float*)dynsmem;
    {
        const int r0 = wm * 32 + (lane >> 2);
        const int c0 = wn * 64 + 2 * (lane & 3);
        #pragma unroll
        for (int mt = 0; mt < 2; ++mt)
            #pragma unroll
            for (int nt = 0; nt < 8; ++nt) {
                const int r = r0 + mt * 16;
                const int c = c0 + nt * 8;
                const float2 v01 = __half22float2(*(const __half2*)&hmast[mt][nt][0]);
                const float2 v23 = __half22float2(*(const __half2*)&hmast[mt][nt][1]);
                *(float2*)&sg[r * SG_STRIDE + c]       = v01;
                *(float2*)&sg[(r + 8) * SG_STRIDE + c] = v23;
            }
    }
    __syncthreads();

    // fused LSTM elementwise: 128 rows x 32 cols = 4096 outputs, 16/thread
    #pragma unroll 4
    for (int it = 0; it < 16; ++it) {
        const int idx = it * 256 + tid;
        const int r  = idx >> 5;
        const int jj = idx & 31;
        const float gi = sg[r * SG_STRIDE +      jj] + sbias[     jj];
        const float gf = sg[r * SG_STRIDE + 32 + jj] + sbias[32 + jj];
        const float gg = sg[r * SG_STRIDE + 64 + jj] + sbias[64 + jj];
        const float go = sg[r * SG_STRIDE + 96 + jj] + sbias[96 + jj];
        const size_t gp = (size_t)(mrow + r) * HID + jbase + jj;
        const float cc = sigf(gf) * c_in[gp] + sigf(gi) * tanhf_fast(gg);
        c_out[gp] = cc;
        h_out[gp] = sigf(go) * tanhf_fast(cc);
    }
}

// ---------------- host launcher ----------------

extern "C" void kernel_launch(void* const* d_in, const int* in_sizes, int n_in,
                              void* d_out, int out_size)
{
    (void)in_sizes; (void)n_in; (void)out_size;
    const float* x  = (const float*)d_in[0];
    const float* h  = (const float*)d_in[1];
    const float* c  = (const float*)d_in[2];
    const float* Wi = (const float*)d_in[3];
    const float* Wh = (const float*)d_in[4];
    const float* bi = (const float*)d_in[5];
    const float* bh = (const float*)d_in[6];
    float* hout = (float*)d_out;
    float* cout = hout + (size_t)BATCH * HID;

    // pass 1: single conversion kernel (xh + weights)
    {
        const size_t n = (size_t)(BATCH + 1024) * KDIM / 8;
        conv_all_kernel<<<(unsigned)((n + 255) / 256), 256>>>(x, h, Wi, Wh);
    }

    // pass 2: GEMM + LSTM. grid: 512 m-tiles x 8 j-slices (adjacent bids
    // share A rows -> L2 dedup). 2 CTAs/SM, 16 warps/SM.
    cudaFuncSetAttribute(lstm_gemm_kernel,
                         cudaFuncAttributeMaxDynamicSharedMemorySize, DYN_SMEM);
    lstm_gemm_kernel<<<(BATCH / M_TILE) * 8, 256, DYN_SMEM>>>(c, bi, bh, hout, cout);
}